// round 8
// baseline (speedup 1.0000x reference)
#include <cuda_runtime.h>
#include <math_constants.h>

// out[n] = h( max_l min_f max_c |A[n,l,c] - B[c,f]| ),  h(D) = t/(1+t)^2, t = exp(-10D)
// min_f max_c |.| is an exact L-inf nearest-neighbor query over 2048 B points.
// Grid-binned spiral search: ring r prunes when best <= (r-1)*h (conservative),
// so the selected min is bit-identical to brute force.
// Stateless: one block per n writes out[n] directly (graph-replay safe).

#define NB 64
#define LB 512
#define FB 2048
#define THREADS 512
#define NWARP 16
#define G 64
#define NCELL (G * G)
#define PPT (FB / THREADS)          // 4 B-points per thread
#define CPT (NCELL / THREADS)       // 8 cells per thread

__global__ __launch_bounds__(THREADS)
void psl_nn_kernel(const float* __restrict__ A, const float* __restrict__ B,
                   float* __restrict__ out)
{
    __shared__ __align__(16) float2 sPts[FB];        // 16 KB: B sorted by cell
    __shared__ unsigned int   sCur[NCELL];           // 16 KB: counts -> cursor -> cell end
    __shared__ unsigned short sStart[NCELL];         //  8 KB: cell start offsets
    __shared__ float sRed[NWARP * 4];
    __shared__ float sParams[4];                     // minx, miny, h, 1/h

    const int tid  = threadIdx.x;
    const int lane = tid & 31;
    const int wid  = tid >> 5;
    const int n    = blockIdx.x;

    // Query point for this thread (thread == l).
    const float2 a = reinterpret_cast<const float2*>(A)[(size_t)n * LB + tid];

    // ---- zero counts ----
    #pragma unroll
    for (int k = 0; k < CPT; k++) sCur[tid + k * THREADS] = 0u;

    // ---- load B, local bbox ----
    float2 bp[PPT];
    float mnx = CUDART_INF_F, mxx = -CUDART_INF_F;
    float mny = CUDART_INF_F, mxy = -CUDART_INF_F;
    #pragma unroll
    for (int k = 0; k < PPT; k++) {
        int i = tid + k * THREADS;
        bp[k] = make_float2(B[i], B[FB + i]);
        mnx = fminf(mnx, bp[k].x); mxx = fmaxf(mxx, bp[k].x);
        mny = fminf(mny, bp[k].y); mxy = fmaxf(mxy, bp[k].y);
    }
    #pragma unroll
    for (int off = 16; off; off >>= 1) {
        mnx = fminf(mnx, __shfl_xor_sync(~0u, mnx, off));
        mxx = fmaxf(mxx, __shfl_xor_sync(~0u, mxx, off));
        mny = fminf(mny, __shfl_xor_sync(~0u, mny, off));
        mxy = fmaxf(mxy, __shfl_xor_sync(~0u, mxy, off));
    }
    if (lane == 0) {
        sRed[wid]             = mnx;
        sRed[NWARP + wid]     = mxx;
        sRed[2 * NWARP + wid] = mny;
        sRed[3 * NWARP + wid] = mxy;
    }
    __syncthreads();
    if (wid == 0) {
        float a0 = (lane < NWARP) ? sRed[lane]             :  CUDART_INF_F;
        float a1 = (lane < NWARP) ? sRed[NWARP + lane]     : -CUDART_INF_F;
        float a2 = (lane < NWARP) ? sRed[2 * NWARP + lane] :  CUDART_INF_F;
        float a3 = (lane < NWARP) ? sRed[3 * NWARP + lane] : -CUDART_INF_F;
        #pragma unroll
        for (int off = 8; off; off >>= 1) {
            a0 = fminf(a0, __shfl_xor_sync(~0u, a0, off));
            a1 = fmaxf(a1, __shfl_xor_sync(~0u, a1, off));
            a2 = fminf(a2, __shfl_xor_sync(~0u, a2, off));
            a3 = fmaxf(a3, __shfl_xor_sync(~0u, a3, off));
        }
        if (lane == 0) {
            float h = fmaxf(fmaxf(a1 - a0, a3 - a2) * (1.000002f / G), 1e-30f);
            sParams[0] = a0; sParams[1] = a2; sParams[2] = h; sParams[3] = 1.0f / h;
        }
    }
    __syncthreads();

    const float pminx = sParams[0], pminy = sParams[1];
    const float h = sParams[2], inv = sParams[3];

    // ---- histogram ----
    int cellk[PPT];
    #pragma unroll
    for (int k = 0; k < PPT; k++) {
        int ci = min(G - 1, max(0, (int)((bp[k].x - pminx) * inv)));
        int cj = min(G - 1, max(0, (int)((bp[k].y - pminy) * inv)));
        cellk[k] = cj * G + ci;
        atomicAdd(&sCur[cellk[k]], 1u);
    }
    __syncthreads();

    // ---- exclusive scan: counts (sCur) -> sStart; then sCur = cursor ----
    {
        unsigned int c[CPT], s = 0;
        const int base = tid * CPT;
        #pragma unroll
        for (int k = 0; k < CPT; k++) { c[k] = sCur[base + k]; s += c[k]; }
        unsigned int incl = s;
        #pragma unroll
        for (int off = 1; off < 32; off <<= 1) {
            unsigned int v = __shfl_up_sync(~0u, incl, off);
            if (lane >= off) incl += v;
        }
        if (lane == 31) ((unsigned int*)sRed)[wid] = incl;
        __syncthreads();
        unsigned int warpOff = 0;
        #pragma unroll
        for (int w = 0; w < NWARP; w++)
            if (w < wid) warpOff += ((unsigned int*)sRed)[w];
        unsigned int run = warpOff + incl - s;
        #pragma unroll
        for (int k = 0; k < CPT; k++) {   // each thread owns its 8 cells exclusively
            sStart[base + k] = (unsigned short)run;
            sCur[base + k]   = run;
            run += c[k];
        }
    }
    __syncthreads();

    // ---- scatter into cell-sorted order ----
    #pragma unroll
    for (int k = 0; k < PPT; k++) {
        unsigned int pos = atomicAdd(&sCur[cellk[k]], 1u);
        sPts[pos] = bp[k];                 // after this, sCur[c] == end of cell c
    }
    __syncthreads();

    // ---- spiral NN search (exact, conservative pruning) ----
    float best = CUDART_INF_F;
    const int qi = min(G - 1, max(0, (int)((a.x - pminx) * inv)));
    const int qj = min(G - 1, max(0, (int)((a.y - pminy) * inv)));

    for (int r = 0; r < G; r++) {
        if (best <= (float)(r - 1) * h * 0.999f) break;
        const int i0 = max(qi - r, 0), i1 = min(qi + r, G - 1);
        const int jt = qj - r, jb = qj + r;

        if (jt >= 0) {   // top row: cells contiguous in sorted order
            unsigned int k = sStart[jt * G + i0];
            unsigned int e = sCur[jt * G + i1];
            for (; k < e; k++) {
                float2 p = sPts[k];
                best = fminf(best, fmaxf(fabsf(a.x - p.x), fabsf(a.y - p.y)));
            }
        }
        if (r > 0) {
            if (jb <= G - 1) {   // bottom row
                unsigned int k = sStart[jb * G + i0];
                unsigned int e = sCur[jb * G + i1];
                for (; k < e; k++) {
                    float2 p = sPts[k];
                    best = fminf(best, fmaxf(fabsf(a.x - p.x), fabsf(a.y - p.y)));
                }
            }
            const int jj0 = max(qj - r + 1, 0), jj1 = min(qj + r - 1, G - 1);
            const int il = qi - r, ir = qi + r;
            for (int j = jj0; j <= jj1; j++) {
                if (il >= 0) {
                    unsigned int k = sStart[j * G + il];
                    unsigned int e = sCur[j * G + il];
                    for (; k < e; k++) {
                        float2 p = sPts[k];
                        best = fminf(best, fmaxf(fabsf(a.x - p.x), fabsf(a.y - p.y)));
                    }
                }
                if (ir <= G - 1) {
                    unsigned int k = sStart[j * G + ir];
                    unsigned int e = sCur[j * G + ir];
                    for (; k < e; k++) {
                        float2 p = sPts[k];
                        best = fminf(best, fmaxf(fabsf(a.x - p.x), fabsf(a.y - p.y)));
                    }
                }
            }
        }
    }

    // ---- block max over the 512 l's, apply h(D), write out[n] ----
    #pragma unroll
    for (int off = 16; off; off >>= 1)
        best = fmaxf(best, __shfl_xor_sync(~0u, best, off));
    if (lane == 0) sRed[wid] = best;
    __syncthreads();
    if (tid == 0) {
        float D = sRed[0];
        #pragma unroll
        for (int w = 1; w < NWARP; w++) D = fmaxf(D, sRed[w]);
        float t = expf(-10.0f * D);
        float u = 1.0f + t;
        out[n] = t / (u * u);
    }
}

extern "C" void kernel_launch(void* const* d_in, const int* in_sizes, int n_in,
                              void* d_out, int out_size) {
    const float* A = (const float*)d_in[0];
    const float* B = (const float*)d_in[1];
    // Defensive: identify by element count (A = 64*512*2 = 65536, B = 2*2048 = 4096).
    if (n_in >= 2 && in_sizes[0] == 4096 && in_sizes[1] == 65536) {
        const float* tmp = A; A = B; B = tmp;
    }
    float* out = (float*)d_out;

    psl_nn_kernel<<<NB, THREADS>>>(A, B, out);
}

// round 9
// speedup vs baseline: 1.6482x; 1.6482x over previous
#include <cuda_runtime.h>
#include <math_constants.h>

// out[n] = h( max_l min_f max_c |A[n,l,c] - B[c,f]| ),  h(D) = t/(1+t)^2, t = exp(-10D)
// min_f max_c |.| = exact L-inf NN over 2048 B points.
// Grid-binned (G=32), fixed 3x3 window, certification best <= 0.999*h
// (any point outside window is > h away), warp-cooperative brute-force
// fallback for uncertified queries => result bit-identical to brute force.
// Counter-based finalize; all __device__ state is 0 at rest (replay-safe).

#define NB 64
#define LB 512
#define FB 2048
#define THREADS 256
#define NWARP 8
#define LCHUNKS 2
#define QPB 256                  // queries per block (1 per thread)
#define G 32
#define NCELL (G * G)            // 1024
#define PPT (FB / THREADS)       // 8 B-points per thread
#define CPT (NCELL / THREADS)    // 4 cells per thread

__device__ unsigned int g_dmax[NB];    // float bits of per-n running max; 0 at rest
__device__ unsigned int g_count[NB];   // arrival counters; 0 at rest

__device__ __forceinline__ unsigned long long pack2(float x, float y) {
    unsigned long long r;
    asm("mov.b64 %0, {%1, %2};" : "=l"(r) : "f"(x), "f"(y));
    return r;
}

// Packed fp32x2 add (Blackwell): both channel diffs in one fma-pipe instr.
__device__ __forceinline__ float2 addf32x2(unsigned long long a, unsigned long long b) {
    unsigned long long d;
    asm("add.rn.f32x2 %0, %1, %2;" : "=l"(d) : "l"(a), "l"(b));
    float lo, hi;
    asm("mov.b64 {%0, %1}, %2;" : "=f"(lo), "=f"(hi) : "l"(d));
    return make_float2(lo, hi);
}

__device__ __forceinline__ float cheb(float2 d) {
    return fmaxf(fabsf(d.x), fabsf(d.y));   // FMNMX with |.| modifiers
}

__global__ __launch_bounds__(THREADS)
void psl_nn2_kernel(const float* __restrict__ A, const float* __restrict__ B,
                    float* __restrict__ out)
{
    __shared__ __align__(16) unsigned long long sPts[FB];  // 16 KB: negated, cell-sorted
    __shared__ unsigned int   sCur[NCELL];                 //  4 KB: counts -> cursor -> end
    __shared__ unsigned short sStart[NCELL];               //  2 KB: cell starts
    __shared__ float          sBest[QPB];                  //  1 KB
    __shared__ unsigned short sQueue[QPB];
    __shared__ unsigned int   sQCount;
    __shared__ float          sRed[NWARP * 4];
    __shared__ unsigned int   sWarpSum[NWARP];
    __shared__ float          sParams[4];                  // minx, miny, h, 1/h

    const int tid  = threadIdx.x;
    const int lane = tid & 31;
    const int wid  = tid >> 5;
    const int n    = blockIdx.x;
    const int qbase = (int)blockIdx.y * QPB;

    // This thread's query.
    const float2 aq = reinterpret_cast<const float2*>(A)[(size_t)n * LB + qbase + tid];

    // ---- init ----
    #pragma unroll
    for (int k = 0; k < CPT; k++) sCur[tid + k * THREADS] = 0u;
    if (tid == 0) sQCount = 0u;

    // ---- load B + bbox ----
    float2 bp[PPT];
    float mnx = CUDART_INF_F, mxx = -CUDART_INF_F;
    float mny = CUDART_INF_F, mxy = -CUDART_INF_F;
    #pragma unroll
    for (int k = 0; k < PPT; k++) {
        int i = tid + k * THREADS;
        bp[k] = make_float2(B[i], B[FB + i]);
        mnx = fminf(mnx, bp[k].x); mxx = fmaxf(mxx, bp[k].x);
        mny = fminf(mny, bp[k].y); mxy = fmaxf(mxy, bp[k].y);
    }
    #pragma unroll
    for (int off = 16; off; off >>= 1) {
        mnx = fminf(mnx, __shfl_xor_sync(~0u, mnx, off));
        mxx = fmaxf(mxx, __shfl_xor_sync(~0u, mxx, off));
        mny = fminf(mny, __shfl_xor_sync(~0u, mny, off));
        mxy = fmaxf(mxy, __shfl_xor_sync(~0u, mxy, off));
    }
    if (lane == 0) {
        sRed[wid]             = mnx;
        sRed[NWARP + wid]     = mxx;
        sRed[2 * NWARP + wid] = mny;
        sRed[3 * NWARP + wid] = mxy;
    }
    __syncthreads();
    if (wid == 0) {
        float a0 = (lane < NWARP) ? sRed[lane]             :  CUDART_INF_F;
        float a1 = (lane < NWARP) ? sRed[NWARP + lane]     : -CUDART_INF_F;
        float a2 = (lane < NWARP) ? sRed[2 * NWARP + lane] :  CUDART_INF_F;
        float a3 = (lane < NWARP) ? sRed[3 * NWARP + lane] : -CUDART_INF_F;
        #pragma unroll
        for (int off = 4; off; off >>= 1) {
            a0 = fminf(a0, __shfl_xor_sync(~0u, a0, off));
            a1 = fmaxf(a1, __shfl_xor_sync(~0u, a1, off));
            a2 = fminf(a2, __shfl_xor_sync(~0u, a2, off));
            a3 = fmaxf(a3, __shfl_xor_sync(~0u, a3, off));
        }
        if (lane == 0) {
            float h = fmaxf(fmaxf(a1 - a0, a3 - a2) * (1.000002f / G), 1e-30f);
            sParams[0] = a0; sParams[1] = a2; sParams[2] = h; sParams[3] = 1.0f / h;
        }
    }
    __syncthreads();

    const float pminx = sParams[0], pminy = sParams[1];
    const float h = sParams[2], inv = sParams[3];

    // ---- histogram ----
    int cellk[PPT];
    #pragma unroll
    for (int k = 0; k < PPT; k++) {
        int ci = min(G - 1, max(0, (int)((bp[k].x - pminx) * inv)));
        int cj = min(G - 1, max(0, (int)((bp[k].y - pminy) * inv)));
        cellk[k] = cj * G + ci;
        atomicAdd(&sCur[cellk[k]], 1u);
    }
    __syncthreads();

    // ---- exclusive scan over 1024 cells (thread owns cells [4tid, 4tid+4)) ----
    {
        unsigned int c[CPT], s = 0;
        const int base = tid * CPT;
        #pragma unroll
        for (int k = 0; k < CPT; k++) { c[k] = sCur[base + k]; s += c[k]; }
        unsigned int incl = s;
        #pragma unroll
        for (int off = 1; off < 32; off <<= 1) {
            unsigned int v = __shfl_up_sync(~0u, incl, off);
            if (lane >= off) incl += v;
        }
        if (lane == 31) sWarpSum[wid] = incl;
        __syncthreads();
        unsigned int warpOff = 0;
        #pragma unroll
        for (int w = 0; w < NWARP; w++)
            if (w < wid) warpOff += sWarpSum[w];
        unsigned int run = warpOff + incl - s;
        #pragma unroll
        for (int k = 0; k < CPT; k++) {
            sStart[base + k] = (unsigned short)run;
            sCur[base + k]   = run;
            run += c[k];
        }
    }
    __syncthreads();

    // ---- scatter (negated, packed) ----
    #pragma unroll
    for (int k = 0; k < PPT; k++) {
        unsigned int pos = atomicAdd(&sCur[cellk[k]], 1u);
        sPts[pos] = pack2(-bp[k].x, -bp[k].y);   // after: sCur[c] == end of cell c
    }
    __syncthreads();

    // ---- fixed 3x3 window scan (uniform control flow) ----
    const unsigned long long qp = pack2(aq.x, aq.y);
    const int qi = min(G - 1, max(0, (int)((aq.x - pminx) * inv)));
    const int qj = min(G - 1, max(0, (int)((aq.y - pminy) * inv)));
    const int i0 = max(qi - 1, 0), i1 = min(qi + 1, G - 1);
    const int j0 = max(qj - 1, 0), j1 = min(qj + 1, G - 1);

    float best = CUDART_INF_F;
    for (int j = j0; j <= j1; j++) {
        unsigned int k = sStart[j * G + i0];
        unsigned int e = sCur[j * G + i1];    // cells row-contiguous in sorted order
        for (; k < e; k++)
            best = fminf(best, cheb(addf32x2(qp, sPts[k])));
    }

    // Certify: any point outside the 3x3 window is > h*(1-ulp) away.
    if (!(best <= 0.999f * h)) {
        unsigned int pos = atomicAdd(&sQCount, 1u);
        sQueue[pos] = (unsigned short)tid;
    }
    sBest[tid] = best;
    __syncthreads();

    // ---- warp-cooperative exact fallback for uncertified queries ----
    const unsigned int qc = sQCount;
    for (unsigned int q = wid; q < qc; q += NWARP) {
        int ql = sQueue[q];
        float2 a2 = reinterpret_cast<const float2*>(A)[(size_t)n * LB + qbase + ql];
        unsigned long long qp2 = pack2(a2.x, a2.y);
        float b = CUDART_INF_F;
        #pragma unroll 4
        for (int k = lane; k < FB; k += 32)
            b = fminf(b, cheb(addf32x2(qp2, sPts[k])));
        #pragma unroll
        for (int off = 16; off; off >>= 1)
            b = fminf(b, __shfl_xor_sync(~0u, b, off));
        if (lane == 0) sBest[ql] = b;
    }
    __syncthreads();

    // ---- block max over QPB queries, combine across blocks ----
    float v = sBest[tid];
    #pragma unroll
    for (int off = 16; off; off >>= 1)
        v = fmaxf(v, __shfl_xor_sync(~0u, v, off));
    if (lane == 0) sRed[wid] = v;
    __syncthreads();

    if (tid == 0) {
        float D = sRed[0];
        #pragma unroll
        for (int w = 1; w < NWARP; w++) D = fmaxf(D, sRed[w]);
        // Nonnegative floats: uint bit-pattern compare == float compare.
        atomicMax(&g_dmax[n], __float_as_uint(D));
        __threadfence();
        unsigned int old = atomicAdd(&g_count[n], 1u);
        if (old == LCHUNKS - 1) {
            __threadfence();
            unsigned int dbits = atomicExch(&g_dmax[n], 0u);   // reset for replay
            atomicExch(&g_count[n], 0u);
            float Df = __uint_as_float(dbits);
            float t = expf(-10.0f * Df);                        // h(D) = t/(1+t)^2
            float u = 1.0f + t;
            out[n] = t / (u * u);
        }
    }
}

extern "C" void kernel_launch(void* const* d_in, const int* in_sizes, int n_in,
                              void* d_out, int out_size) {
    const float* A = (const float*)d_in[0];
    const float* B = (const float*)d_in[1];
    // Defensive: identify by element count (A = 64*512*2 = 65536, B = 2*2048 = 4096).
    if (n_in >= 2 && in_sizes[0] == 4096 && in_sizes[1] == 65536) {
        const float* tmp = A; A = B; B = tmp;
    }
    float* out = (float*)d_out;

    dim3 grid(NB, LCHUNKS);   // 64 x 2 = 128 blocks, one per SM, single wave
    psl_nn2_kernel<<<grid, THREADS>>>(A, B, out);
}

// round 11
// speedup vs baseline: 1.9524x; 1.1845x over previous
#include <cuda_runtime.h>
#include <math_constants.h>

// out[n] = h( max_l min_f max_c |A[n,l,c] - B[c,f]| ),  h(D) = t/(1+t)^2, t = exp(-10D)
// min_f max_c |.| = exact L-inf NN over 2048 B points.
// Fixed-domain grid (G=48 over [-4,4]^2; out-of-domain points clamped for
// BINNING only, stored coords exact): 3x3 window + certification
// best <= 0.999*h. Any point binned >=2 cells away is provably > 0.999h from
// the query (clamping only moves points toward in-domain coordinates), so
// certified results are bit-identical to brute force; uncertified queries are
// recomputed exactly by a warp-cooperative brute-force fallback that
// OVERWRITES their slot in sBest (no masking tricks — R10's bug).
// Queries counting-sorted by cell, fused with the B sort via packed u32
// counts => warp-coherent window scans (broadcast LDS, uniform trip counts).
// Counter finalize; all __device__ state is 0 at rest (graph-replay safe).

#define NB 64
#define LB 512
#define FB 2048
#define THREADS 256
#define NWARP 8
#define LCHUNKS 2
#define QPB 256                  // queries per block (1 per thread)
#define G 48
#define NCELL (G * G)            // 2304
#define PPT (FB / THREADS)       // 8 B-points per thread
#define CPT (NCELL / THREADS)    // 9 cells per thread
#define DOM_LO (-4.0f)
#define CELL_H (8.0f / G)        // 1/6
#define CELL_INV (G / 8.0f)      // 6

__device__ unsigned int g_dmax[NB];    // float bits of per-n running max; 0 at rest
__device__ unsigned int g_count[NB];   // arrival counters; 0 at rest

__device__ __forceinline__ unsigned long long pack2(float x, float y) {
    unsigned long long r;
    asm("mov.b64 %0, {%1, %2};" : "=l"(r) : "f"(x), "f"(y));
    return r;
}
__device__ __forceinline__ float2 unpack2(unsigned long long v) {
    float x, y;
    asm("mov.b64 {%0, %1}, %2;" : "=f"(x), "=f"(y) : "l"(v));
    return make_float2(x, y);
}
// Packed fp32x2 add (Blackwell): both channel diffs in one fma-pipe instr.
__device__ __forceinline__ float2 addf32x2(unsigned long long a, unsigned long long b) {
    unsigned long long d;
    asm("add.rn.f32x2 %0, %1, %2;" : "=l"(d) : "l"(a), "l"(b));
    float lo, hi;
    asm("mov.b64 {%0, %1}, %2;" : "=f"(lo), "=f"(hi) : "l"(d));
    return make_float2(lo, hi);
}
__device__ __forceinline__ float cheb(float2 d) {
    return fmaxf(fabsf(d.x), fabsf(d.y));   // FMNMX with |.| modifiers
}
__device__ __forceinline__ int cellcoord(float v) {
    return min(G - 1, max(0, (int)((v - DOM_LO) * CELL_INV)));
}

__global__ __launch_bounds__(THREADS)
void psl_nn4_kernel(const float* __restrict__ A, const float* __restrict__ B,
                    float* __restrict__ out)
{
    __shared__ __align__(16) unsigned long long sPts[FB];    // 16 KB: -B, cell-sorted
    __shared__ __align__(16) unsigned long long sQPts[QPB];  //  2 KB: queries, cell-sorted
    __shared__ unsigned int   sCur[NCELL];    // 9.2 KB: packed bcnt|qcnt<<16 -> cursor -> end
    __shared__ unsigned int   sStart[NCELL];  // 9.2 KB: packed starts (b low16, q high16)
    __shared__ float          sBest[QPB];     //  1 KB: exact per-sorted-query result
    __shared__ unsigned short sQueue[QPB];
    __shared__ unsigned int   sQCount;
    __shared__ float          sRed[NWARP];
    __shared__ unsigned int   sWarpSum[NWARP];

    const int tid  = threadIdx.x;
    const int lane = tid & 31;
    const int wid  = tid >> 5;
    const int n    = blockIdx.x;
    const int qbase = (int)blockIdx.y * QPB;

    // ---- init counts ----
    #pragma unroll
    for (int k = 0; k < CPT; k++) sCur[tid + k * THREADS] = 0u;
    if (tid == 0) sQCount = 0u;

    // This thread's query (A layout: [n][l][2] -> float2).
    const float2 aq = reinterpret_cast<const float2*>(A)[(size_t)n * LB + qbase + tid];
    const int qcell = cellcoord(aq.y) * G + cellcoord(aq.x);

    // ---- load B, compute cells ----
    float2 bp[PPT];
    int bcell[PPT];
    #pragma unroll
    for (int k = 0; k < PPT; k++) {
        int i = tid + k * THREADS;
        bp[k] = make_float2(B[i], B[FB + i]);
        bcell[k] = cellcoord(bp[k].y) * G + cellcoord(bp[k].x);
    }
    __syncthreads();   // counts zeroed

    // ---- fused histograms: B in low 16 bits, queries in high 16 ----
    #pragma unroll
    for (int k = 0; k < PPT; k++) atomicAdd(&sCur[bcell[k]], 1u);
    atomicAdd(&sCur[qcell], 1u << 16);
    __syncthreads();

    // ---- one exclusive scan over 2304 packed counts (fields never collide:
    //      B total 2048 in low half, Q total 256 in high half) ----
    {
        unsigned int c[CPT], s = 0;
        const int base = tid * CPT;
        #pragma unroll
        for (int k = 0; k < CPT; k++) { c[k] = sCur[base + k]; s += c[k]; }
        unsigned int incl = s;
        #pragma unroll
        for (int off = 1; off < 32; off <<= 1) {
            unsigned int v = __shfl_up_sync(~0u, incl, off);
            if (lane >= off) incl += v;
        }
        if (lane == 31) sWarpSum[wid] = incl;
        __syncthreads();
        unsigned int warpOff = 0;
        #pragma unroll
        for (int w = 0; w < NWARP; w++)
            if (w < wid) warpOff += sWarpSum[w];
        unsigned int run = warpOff + incl - s;
        #pragma unroll
        for (int k = 0; k < CPT; k++) {
            sStart[base + k] = run;
            sCur[base + k]   = run;    // becomes the scatter cursor
            run += c[k];
        }
    }
    __syncthreads();

    // ---- fused scatter: B (negated) and queries into cell-sorted order ----
    #pragma unroll
    for (int k = 0; k < PPT; k++) {
        unsigned int pos = atomicAdd(&sCur[bcell[k]], 1u) & 0xFFFFu;
        sPts[pos] = pack2(-bp[k].x, -bp[k].y);
    }
    {
        unsigned int qpos = atomicAdd(&sCur[qcell], 1u << 16) >> 16;
        sQPts[qpos] = pack2(aq.x, aq.y);
    }
    __syncthreads();   // after this: sCur low16 == B end-of-cell

    // ---- warp-coherent 3x3 window scan (thread t = t-th sorted query) ----
    const unsigned long long qp = sQPts[tid];
    const float2 q = unpack2(qp);
    const int qi = cellcoord(q.x), qj = cellcoord(q.y);
    const int i0 = max(qi - 1, 0), i1 = min(qi + 1, G - 1);
    const int j0 = max(qj - 1, 0), j1 = min(qj + 1, G - 1);

    float best = CUDART_INF_F;
    for (int j = j0; j <= j1; j++) {
        unsigned int k = sStart[j * G + i0] & 0xFFFFu;
        unsigned int e = sCur[j * G + i1] & 0xFFFFu;   // cells row-contiguous
        for (; k < e; k++)
            best = fminf(best, cheb(addf32x2(qp, sPts[k])));
    }
    sBest[tid] = best;   // exact iff certified; fallback overwrites otherwise

    // Certify: any point binned outside the 3x3 window is > 0.999h away.
    if (!(best <= 0.999f * CELL_H)) {
        unsigned int pos = atomicAdd(&sQCount, 1u);
        sQueue[pos] = (unsigned short)tid;
    }
    __syncthreads();

    // ---- exact warp-cooperative fallback OVERWRITES uncertified slots ----
    const unsigned int qc = sQCount;
    for (unsigned int iq = wid; iq < qc; iq += NWARP) {
        int ql = sQueue[iq];
        unsigned long long qp2 = sQPts[ql];
        float b = CUDART_INF_F;
        #pragma unroll 4
        for (int k = lane; k < FB; k += 32)
            b = fminf(b, cheb(addf32x2(qp2, sPts[k])));
        #pragma unroll
        for (int off = 16; off; off >>= 1)
            b = fminf(b, __shfl_xor_sync(~0u, b, off));
        if (lane == 0) sBest[ql] = b;
    }
    __syncthreads();

    // ---- block max over the QPB exact per-query results ----
    float v = sBest[tid];
    #pragma unroll
    for (int off = 16; off; off >>= 1)
        v = fmaxf(v, __shfl_xor_sync(~0u, v, off));
    if (lane == 0) sRed[wid] = v;
    __syncthreads();

    if (tid == 0) {
        float D = sRed[0];
        #pragma unroll
        for (int w = 1; w < NWARP; w++) D = fmaxf(D, sRed[w]);
        // Nonnegative floats: uint bit-pattern compare == float compare.
        atomicMax(&g_dmax[n], __float_as_uint(D));
        __threadfence();
        unsigned int old = atomicAdd(&g_count[n], 1u);
        if (old == LCHUNKS - 1) {
            __threadfence();
            unsigned int dbits = atomicExch(&g_dmax[n], 0u);   // reset for replay
            atomicExch(&g_count[n], 0u);
            float Df = __uint_as_float(dbits);
            float t = expf(-10.0f * Df);                        // h(D) = t/(1+t)^2
            float u = 1.0f + t;
            out[n] = t / (u * u);
        }
    }
}

extern "C" void kernel_launch(void* const* d_in, const int* in_sizes, int n_in,
                              void* d_out, int out_size) {
    const float* A = (const float*)d_in[0];
    const float* B = (const float*)d_in[1];
    // Defensive: identify by element count (A = 64*512*2 = 65536, B = 2*2048 = 4096).
    if (n_in >= 2 && in_sizes[0] == 4096 && in_sizes[1] == 65536) {
        const float* tmp = A; A = B; B = tmp;
    }
    float* out = (float*)d_out;

    dim3 grid(NB, LCHUNKS);   // 64 x 2 = 128 blocks
    psl_nn4_kernel<<<grid, THREADS>>>(A, B, out);
}